// round 12
// baseline (speedup 1.0000x reference)
#include <cuda_runtime.h>
#include <math.h>

#define BB 8
#define SS 4096
#define HH 4096
#define DD 128
#define NMAX 64
#define NT 64
#define HT 64            /* HH / NT */
#define TPB 128
#define SPL 2            /* row split: block z handles rows n = z, z+2, ... */
#define ARR_TARGET (NT * SPL)   /* 128 blocks per batch */

// -------- persistent scratch: zero at load; tail re-zeros each replay ------
__device__ float g_K[BB][NMAX][DD];   // 256 KB, RED-accumulated
__device__ float g_Q[BB][DD];
__device__ float g_V[BB][NMAX];
__device__ float g_rew[BB];
__device__ int   g_arrive[BB];        // per-batch arrival counters
__device__ int   g_done;              // cross-batch arrival counter

__device__ __forceinline__ void red_f32(float* p, float v) {
    asm volatile("red.global.add.f32 [%0], %1;" :: "l"(p), "f"(v) : "memory");
}
__device__ __forceinline__ void red_v2(float* p, float x, float y) {
    asm volatile("red.global.add.v2.f32 [%0], {%1,%2};"
                 :: "l"(p), "f"(x), "f"(y) : "memory");
}

// ---------------------------------------------------------------------------
// ONE fused kernel. grid=(NT, BB, SPL), 128 threads (thread = output dim d).
// Phase 1 (R7-proven shape): ~21 rows/block, K staged in smem, ONE v2-RED
//          burst at block end. V via warp shfl + scalar RED. Q by owner split.
// Phase 2 (128th block of a batch): attention + reward + re-zero.
// Phase 3 (last batch): pairwise loss + output.
// ---------------------------------------------------------------------------
__global__ void __launch_bounds__(TPB)
k_fused(const float* __restrict__ hid,
        const int*   __restrict__ mask,
        const float* __restrict__ Wq,
        const float* __restrict__ bq,
        const float* __restrict__ Wk,
        const float* __restrict__ bk,
        const float* __restrict__ Wr,
        const float* __restrict__ br,
        float* __restrict__ out, int out_size) {
    const int b     = blockIdx.y;
    const int tile  = blockIdx.x;
    const int split = blockIdx.z;
    const int h0    = tile * HT;
    const int tid   = threadIdx.x;     // == d
    const int lane  = tid & 31, warp = tid >> 5;

    // pool: proj uses [0,2048) as row tile (<=8KB) and [2048,6144) as sK
    // staging (16KB); attention tail reuses the whole 32KB for K.
    __shared__ __align__(16) float pool[NMAX * DD];   // 32 KB
    float* buf = pool;                                 // [NMAX/2][HT]
    float* sK  = pool + (NMAX / 2) * HT;               // [NMAX/2][DD]
    __shared__ float swr[HT];
    __shared__ float qs[DD];
    __shared__ float lg[NMAX];
    __shared__ float sv[NMAX];
    __shared__ int   s_pos[NMAX];
    __shared__ int   s_wsum[4];
    __shared__ int   s_cnt;
    __shared__ int   s_last;

    // ---- issue Wk register preload FIRST (overlaps the scan below) ----
    unsigned long long wk2[HT / 2];
#pragma unroll
    for (int j = 0; j < HT / 2; j++) {
        float w0 = Wk[(size_t)(h0 + 2 * j) * DD + tid];
        float w1 = Wk[(size_t)(h0 + 2 * j + 1) * DD + tid];
        asm("mov.b64 %0,{%1,%2};" : "=l"(wk2[j]) : "f"(w0), "f"(w1));
    }
    if (tid < HT) swr[tid] = Wr[h0 + tid];

    // ---- inline mask scan: SINGLE pass, 128 threads x 32 elements ----
    {
        const int base = tid * 32;
        const int4* m4 = (const int4*)(mask + b * SS + base);
        int v[32];
#pragma unroll
        for (int q = 0; q < 8; q++) {
            int4 t4 = m4[q];
            v[4*q] = t4.x; v[4*q+1] = t4.y; v[4*q+2] = t4.z; v[4*q+3] = t4.w;
        }
        int c = 0;
#pragma unroll
        for (int j = 0; j < 32; j++) c += (v[j] > 0);
        int x = c;
#pragma unroll
        for (int off = 1; off < 32; off <<= 1) {
            int y = __shfl_up_sync(0xffffffffu, x, off);
            if (lane >= off) x += y;
        }
        if (lane == 31) s_wsum[warp] = x;
        __syncthreads();
        int pre = 0;
#pragma unroll
        for (int w = 0; w < 4; w++) pre += (w < warp) ? s_wsum[w] : 0;
        int r = pre + x - c;
#pragma unroll
        for (int j = 0; j < 32; j++) {
            if (v[j] > 0) { if (r < NMAX) s_pos[r] = base + j; r++; }
        }
        if (tid == 0) {
            int tot = s_wsum[0] + s_wsum[1] + s_wsum[2] + s_wsum[3];
            s_cnt = (tot < NMAX) ? tot : NMAX;
        }
        __syncthreads();
    }
    const int cnt  = s_cnt;
    const int last = cnt - 1;
    const int nloc = (cnt > split) ? ((cnt - split + 1) >> 1) : 0;

    // ---- preload this split's sentence-row slices into smem ----
    {
        int tot4 = nloc * (HT / 4);
        float4* b4 = (float4*)buf;
        for (int i = tid; i < tot4; i += TPB) {
            int row = i >> 4;            // HT/4 = 16
            int c4  = i & 15;
            b4[i] = *(const float4*)(hid +
                ((size_t)b * SS + s_pos[split + 2 * row]) * HH + h0 + c4 * 4);
        }
    }
    __syncthreads();

    // ---- mainloop: 2 rows/iter, 4 FFMA2 chains, results staged in sK ----
    int i = 0;
    for (; i + 2 <= nloc; i += 2) {
        const ulonglong2* r0 = (const ulonglong2*)&buf[i * HT];
        const ulonglong2* r1 = (const ulonglong2*)&buf[(i + 1) * HT];
        unsigned long long a00 = 0ull, a01 = 0ull, a10 = 0ull, a11 = 0ull;
#pragma unroll
        for (int j = 0; j < HT / 4; j++) {
            ulonglong2 x0 = r0[j], x1 = r1[j];
            asm("fma.rn.f32x2 %0,%1,%2,%0;" : "+l"(a00) : "l"(x0.x), "l"(wk2[2*j]));
            asm("fma.rn.f32x2 %0,%1,%2,%0;" : "+l"(a10) : "l"(x1.x), "l"(wk2[2*j]));
            asm("fma.rn.f32x2 %0,%1,%2,%0;" : "+l"(a01) : "l"(x0.y), "l"(wk2[2*j+1]));
            asm("fma.rn.f32x2 %0,%1,%2,%0;" : "+l"(a11) : "l"(x1.y), "l"(wk2[2*j+1]));
        }
        float l0,h0f,l1,h1f,l2,h2f,l3,h3f;
        asm("mov.b64 {%0,%1},%2;" : "=f"(l0), "=f"(h0f) : "l"(a00));
        asm("mov.b64 {%0,%1},%2;" : "=f"(l1), "=f"(h1f) : "l"(a01));
        asm("mov.b64 {%0,%1},%2;" : "=f"(l2), "=f"(h2f) : "l"(a10));
        asm("mov.b64 {%0,%1},%2;" : "=f"(l3), "=f"(h3f) : "l"(a11));
        sK[i * DD + tid]       = (l0 + h0f) + (l1 + h1f);
        sK[(i + 1) * DD + tid] = (l2 + h2f) + (l3 + h3f);

        if (tid < HT) {   // V partials for both rows (warps 0,1)
            float vp0 = buf[i * HT + tid] * swr[tid];
            float vp1 = buf[(i + 1) * HT + tid] * swr[tid];
#pragma unroll
            for (int off = 16; off; off >>= 1) {
                vp0 += __shfl_down_sync(0xffffffffu, vp0, off);
                vp1 += __shfl_down_sync(0xffffffffu, vp1, off);
            }
            if (lane == 0) {
                red_f32(&g_V[b][split + 2 * i], vp0);
                red_f32(&g_V[b][split + 2 * (i + 1)], vp1);
            }
        }
    }
    if (i < nloc) {       // odd tail row
        const ulonglong2* r0 = (const ulonglong2*)&buf[i * HT];
        unsigned long long a00 = 0ull, a01 = 0ull;
#pragma unroll
        for (int j = 0; j < HT / 4; j++) {
            ulonglong2 x0 = r0[j];
            asm("fma.rn.f32x2 %0,%1,%2,%0;" : "+l"(a00) : "l"(x0.x), "l"(wk2[2*j]));
            asm("fma.rn.f32x2 %0,%1,%2,%0;" : "+l"(a01) : "l"(x0.y), "l"(wk2[2*j+1]));
        }
        float l0,h0f,l1,h1f;
        asm("mov.b64 {%0,%1},%2;" : "=f"(l0), "=f"(h0f) : "l"(a00));
        asm("mov.b64 {%0,%1},%2;" : "=f"(l1), "=f"(h1f) : "l"(a01));
        sK[i * DD + tid] = (l0 + h0f) + (l1 + h1f);
        if (tid < HT) {
            float vp0 = buf[i * HT + tid] * swr[tid];
#pragma unroll
            for (int off = 16; off; off >>= 1)
                vp0 += __shfl_down_sync(0xffffffffu, vp0, off);
            if (lane == 0) red_f32(&g_V[b][split + 2 * i], vp0);
        }
    }

    // ---- Q: only the split owning the last sentence row ----
    if (((cnt - 1) & 1) == split) {
        int il = (cnt - 1 - split) >> 1;
        const float* srow = &buf[il * HT];
        float aq0 = 0.0f, aq1 = 0.0f;
#pragma unroll
        for (int j = 0; j < HT; j += 2) {
            aq0 += srow[j]     * Wq[(size_t)(h0 + j) * DD + tid];
            aq1 += srow[j + 1] * Wq[(size_t)(h0 + j + 1) * DD + tid];
        }
        float aq = aq0 + aq1;
        float pq = __shfl_xor_sync(0xffffffffu, aq, 1);
        if ((tid & 1) == 0) red_v2(&g_Q[b][tid], aq, pq);
    }
    __syncthreads();

    // ---- flush staged K rows with one v2-RED burst ----
    for (int j = tid; j < nloc * (DD / 2); j += TPB) {
        int row = j >> 6, dh = j & 63;
        float2 v = *(const float2*)&sK[row * DD + 2 * dh];
        red_v2(&g_K[b][split + 2 * row][2 * dh], v.x, v.y);
    }

    // ---- per-batch arrival: 128th block proceeds to attention ----
    __threadfence();
    __syncthreads();
    if (tid == 0) {
        int old = atomicAdd(&g_arrive[b], 1);
        s_last = (old == ARR_TARGET - 1);
        if (s_last) g_arrive[b] = 0;     // reset for next replay
    }
    __syncthreads();
    if (!s_last) return;
    __threadfence();                     // acquire: make all REDs visible

    // =================== attention tail (1 block per batch) ================
    // burst g_K[b] into smem pool; zero it behind the read
    {
        float4* b4 = (float4*)pool;
        float4 z = make_float4(0.f, 0.f, 0.f, 0.f);
        int tot = cnt * (DD / 4);
        for (int ii = tid; ii < tot; ii += TPB) {
            int row = ii >> 5, c4 = ii & 31;
            float4 v = *(const float4*)&g_K[b][row][c4 * 4];
            b4[ii] = v;
            *(float4*)&g_K[b][row][c4 * 4] = z;
        }
    }
    if (tid < NMAX) { sv[tid] = g_V[b][tid]; g_V[b][tid] = 0.0f; }

    const float LN_THETA = 9.210340371976184f;   // ln(10000)

    // RoPE the single q row at rank = last; zero g_Q behind the read
    {
        float freq = __expf(-LN_THETA * (float)(2 * (tid >> 1)) * (1.0f / 128.0f));
        float qv = g_Q[b][tid] + bq[tid];
        g_Q[b][tid] = 0.0f;
        float a = (float)last * freq;
        float cq = __cosf(a), sq = __sinf(a);
        float qp = __shfl_xor_sync(0xffffffffu, qv, 1);
        qs[tid] = ((tid & 1) == 0) ? (qv * cq - qp * sq) : (qp * sq + qv * cq);
    }
    __syncthreads();

    // logits from smem: warp w handles n = w, w+4, ...
    float fr[4];
#pragma unroll
    for (int s4 = 0; s4 < 4; s4++) {
        int dd = lane + s4 * 32;
        fr[s4] = __expf(-LN_THETA * (float)(2 * (dd >> 1)) * (1.0f / 128.0f));
    }
    for (int n = warp; n < cnt; n += 4) {
        float dot = 0.0f;
        float nf = (float)n;
#pragma unroll
        for (int s4 = 0; s4 < 4; s4++) {
            int dd = lane + s4 * 32;
            float kv = pool[n * DD + dd] + bk[dd];
            float a = nf * fr[s4];
            float cn = __cosf(a), sn = __sinf(a);
            float kp = __shfl_xor_sync(0xffffffffu, kv, 1);
            float kr = ((dd & 1) == 0) ? (kv * cn - kp * sn) : (kp * sn + kv * cn);
            dot += qs[dd] * kr;
        }
#pragma unroll
        for (int off = 16; off; off >>= 1)
            dot += __shfl_xor_sync(0xffffffffu, dot, off);
        if (lane == 0) lg[n] = dot * 0.08838834764831845f;  // 1/sqrt(128)
    }
    __syncthreads();

    // warp-parallel softmax + reward; then cross-batch join + loss
    if (warp == 0) {
        const float NEG = -3.0e38f;
        int n0 = lane, n1 = lane + 32;
        bool v0ok = (n0 < cnt), v1ok = (n1 < cnt);
        float l0 = v0ok ? lg[n0] : NEG;
        float l1 = v1ok ? lg[n1] : NEG;
        float mx = fmaxf(l0, l1);
#pragma unroll
        for (int off = 16; off; off >>= 1)
            mx = fmaxf(mx, __shfl_xor_sync(0xffffffffu, mx, off));

        float br0 = br[0];
        float e0 = v0ok ? __expf(l0 - mx) : 0.0f;
        float e1 = v1ok ? __expf(l1 - mx) : 0.0f;
        float vn0 = v0ok ? (sv[n0] + br0) : 0.0f;
        float vp0 = (v0ok && n0 > 0) ? (sv[n0 - 1] + br0) : 0.0f;
        float vn1 = v1ok ? (sv[n1] + br0) : 0.0f;
        float vp1 = v1ok ? (sv[n1 - 1] + br0) : 0.0f;
        float sum = e0 + e1;
        float rew = e0 * (vn0 - vp0) + e1 * (vn1 - vp1);
#pragma unroll
        for (int off = 16; off; off >>= 1) {
            sum += __shfl_xor_sync(0xffffffffu, sum, off);
            rew += __shfl_xor_sync(0xffffffffu, rew, off);
        }
        if (lane == 0) {
            g_rew[b] = rew / sum;
            __threadfence();
            int old2 = atomicAdd(&g_done, 1);
            if (old2 == BB - 1) {        // last batch: pairwise loss + output
                __threadfence();
                float r[BB];
#pragma unroll
                for (int k = 0; k < BB; k++) r[k] = g_rew[k];
                float loss = 0.0f;
#pragma unroll
                for (int k = 0; k < 4; k++) {
                    float x = r[k] - r[k + 4];
                    loss += (x >= 0.0f) ? log1pf(expf(-x))
                                        : (-x + log1pf(expf(x)));
                }
                loss *= 0.25f;
                if (out_size >= 9) {
                    out[0] = loss;
                    for (int k = 0; k < 8; k++) out[1 + k] = r[k];
                } else if (out_size == 8) {
                    for (int k = 0; k < 8; k++) out[k] = r[k];
                } else {
                    out[0] = loss;
                }
                g_done = 0;              // reset for next replay
            }
        }
    }
}

// ---------------------------------------------------------------------------
extern "C" void kernel_launch(void* const* d_in, const int* in_sizes, int n_in,
                              void* d_out, int out_size) {
    const float* hid  = (const float*)d_in[0];
    const int*   mask = (const int*)  d_in[1];
    const float* Wq   = (const float*)d_in[2];
    const float* bq   = (const float*)d_in[3];
    const float* Wk   = (const float*)d_in[4];
    const float* bk   = (const float*)d_in[5];
    const float* Wr   = (const float*)d_in[6];
    const float* br   = (const float*)d_in[7];
    float* out = (float*)d_out;

    k_fused<<<dim3(NT, BB, SPL), TPB>>>(hid, mask, Wq, bq, Wk, bk, Wr, br,
                                        out, out_size);
}

// round 13
// speedup vs baseline: 1.0057x; 1.0057x over previous
#include <cuda_runtime.h>
#include <math.h>

#define BB 8
#define SS 4096
#define HH 4096
#define DD 128
#define NMAX 64
#define NT 64
#define HT 64            /* h-slice per block */
#define HHALF 32         /* h per thread-half */
#define TPB 256
#define CHUNK 32
#define ARR_TARGET NT    /* 64 blocks per batch */

// -------- persistent scratch: zero at load; tail re-zeros each replay ------
__device__ float g_K[BB][NMAX][DD];   // 256 KB, RED-accumulated
__device__ float g_Q[BB][DD];
__device__ float g_V[BB][NMAX];
__device__ float g_rew[BB];
__device__ int   g_arrive[BB];        // per-batch arrival counters
__device__ int   g_done;              // cross-batch arrival counter

__device__ __forceinline__ void red_f32(float* p, float v) {
    asm volatile("red.global.add.f32 [%0], %1;" :: "l"(p), "f"(v) : "memory");
}
__device__ __forceinline__ void red_v2(float* p, float x, float y) {
    asm volatile("red.global.add.v2.f32 [%0], {%1,%2};"
                 :: "l"(p), "f"(x), "f"(y) : "memory");
}

// ---------------------------------------------------------------------------
// ONE fused kernel. grid=(NT, BB), 256 threads.
// Thread (d = tid&127, half = tid>>7) covers h in [h0+half*32, h0+half*32+32).
// K partials: halves stage to sK0/sK1 in smem; combine pass does ONE v2-RED
// per (row,d) -- same RED count as R8, double the warps, half the chain.
// Rows processed in chunks of 32 to bound smem.
// ---------------------------------------------------------------------------
__global__ void __launch_bounds__(TPB, 3)
k_fused(const float* __restrict__ hid,
        const int*   __restrict__ mask,
        const float* __restrict__ Wq,
        const float* __restrict__ bq,
        const float* __restrict__ Wk,
        const float* __restrict__ bk,
        const float* __restrict__ Wr,
        const float* __restrict__ br,
        float* __restrict__ out, int out_size) {
    const int b    = blockIdx.y;
    const int tile = blockIdx.x;
    const int h0   = tile * HT;
    const int tid  = threadIdx.x;
    const int lane = tid & 31, warp = tid >> 5;    // 8 warps
    const int d    = tid & (DD - 1);
    const int half = tid >> 7;                      // 0/1
    const int hb   = h0 + half * HHALF;

    // pool (40KB): proj: buf = pool[0:2048) rows (CHUNK x HT),
    //              sK0 = pool[2048:6144), sK1 = pool[6144:10240)
    //              tail: pool[0 : cnt*DD) for K (max 8192 floats)
    __shared__ __align__(16) float pool[2048 + 2 * CHUNK * DD];
    float* buf = pool;
    float* sK0 = pool + 2048;
    float* sK1 = pool + 2048 + CHUNK * DD;
    __shared__ float swr[HT];
    __shared__ float qs[DD];
    __shared__ float lg[NMAX];
    __shared__ float sv[NMAX];
    __shared__ int   s_pos[NMAX];
    __shared__ int   s_wsum[8];
    __shared__ int   s_cnt;
    __shared__ int   s_last;

    // ---- Wk register preload (32 regs), issued first ----
    unsigned long long wk2[HHALF / 2];              // 16 f32x2
#pragma unroll
    for (int j = 0; j < HHALF / 2; j++) {
        float w0 = Wk[(size_t)(hb + 2 * j) * DD + d];
        float w1 = Wk[(size_t)(hb + 2 * j + 1) * DD + d];
        asm("mov.b64 %0,{%1,%2};" : "=l"(wk2[j]) : "f"(w0), "f"(w1));
    }
    if (tid < HT) swr[tid] = Wr[h0 + tid];

    // ---- mask scan: single pass, 256 threads x 16 elements ----
    {
        const int base = tid * 16;
        const int4* m4 = (const int4*)(mask + b * SS + base);
        int v[16];
#pragma unroll
        for (int q = 0; q < 4; q++) {
            int4 t4 = m4[q];
            v[4*q] = t4.x; v[4*q+1] = t4.y; v[4*q+2] = t4.z; v[4*q+3] = t4.w;
        }
        int c = 0;
#pragma unroll
        for (int j = 0; j < 16; j++) c += (v[j] > 0);
        int x = c;
#pragma unroll
        for (int off = 1; off < 32; off <<= 1) {
            int y = __shfl_up_sync(0xffffffffu, x, off);
            if (lane >= off) x += y;
        }
        if (lane == 31) s_wsum[warp] = x;
        __syncthreads();
        int pre = 0;
#pragma unroll
        for (int w = 0; w < 8; w++) pre += (w < warp) ? s_wsum[w] : 0;
        int r = pre + x - c;
#pragma unroll
        for (int j = 0; j < 16; j++) {
            if (v[j] > 0) { if (r < NMAX) s_pos[r] = base + j; r++; }
        }
        if (tid == 0) {
            int tot = 0;
#pragma unroll
            for (int w = 0; w < 8; w++) tot += s_wsum[w];
            s_cnt = (tot < NMAX) ? tot : NMAX;
        }
        __syncthreads();
    }
    const int cnt  = s_cnt;
    const int last = cnt - 1;

    // ================== chunked projection ==================
    for (int c0 = 0; c0 < cnt; c0 += CHUNK) {
        const int rc = (cnt - c0 < CHUNK) ? (cnt - c0) : CHUNK;

        // preload chunk rows (rc x HT floats) into buf
        {
            int tot4 = rc * (HT / 4);
            float4* b4 = (float4*)buf;
            for (int i = tid; i < tot4; i += TPB) {
                int row = i >> 4;          // HT/4 = 16
                int c4  = i & 15;
                b4[i] = *(const float4*)(hid +
                    ((size_t)b * SS + s_pos[c0 + row]) * HH + h0 + c4 * 4);
            }
        }
        __syncthreads();

        // mainloop: 2 rows/iter, 4 FFMA2 chains over 8 j-steps
        float* sKh = half ? sK1 : sK0;
        int i = 0;
        for (; i + 2 <= rc; i += 2) {
            const ulonglong2* r0 = (const ulonglong2*)&buf[i * HT + half * HHALF];
            const ulonglong2* r1 = (const ulonglong2*)&buf[(i + 1) * HT + half * HHALF];
            unsigned long long a00 = 0ull, a01 = 0ull, a10 = 0ull, a11 = 0ull;
#pragma unroll
            for (int j = 0; j < HHALF / 4; j++) {      // 8 iterations
                ulonglong2 x0 = r0[j], x1 = r1[j];
                asm("fma.rn.f32x2 %0,%1,%2,%0;" : "+l"(a00) : "l"(x0.x), "l"(wk2[2*j]));
                asm("fma.rn.f32x2 %0,%1,%2,%0;" : "+l"(a10) : "l"(x1.x), "l"(wk2[2*j]));
                asm("fma.rn.f32x2 %0,%1,%2,%0;" : "+l"(a01) : "l"(x0.y), "l"(wk2[2*j+1]));
                asm("fma.rn.f32x2 %0,%1,%2,%0;" : "+l"(a11) : "l"(x1.y), "l"(wk2[2*j+1]));
            }
            float l0,h0f,l1,h1f,l2,h2f,l3,h3f;
            asm("mov.b64 {%0,%1},%2;" : "=f"(l0), "=f"(h0f) : "l"(a00));
            asm("mov.b64 {%0,%1},%2;" : "=f"(l1), "=f"(h1f) : "l"(a01));
            asm("mov.b64 {%0,%1},%2;" : "=f"(l2), "=f"(h2f) : "l"(a10));
            asm("mov.b64 {%0,%1},%2;" : "=f"(l3), "=f"(h3f) : "l"(a11));
            sKh[i * DD + d]       = (l0 + h0f) + (l1 + h1f);
            sKh[(i + 1) * DD + d] = (l2 + h2f) + (l3 + h3f);

            if (tid < HT) {   // V partials (warps 0,1)
                float vp0 = buf[i * HT + tid] * swr[tid];
                float vp1 = buf[(i + 1) * HT + tid] * swr[tid];
#pragma unroll
                for (int off = 16; off; off >>= 1) {
                    vp0 += __shfl_down_sync(0xffffffffu, vp0, off);
                    vp1 += __shfl_down_sync(0xffffffffu, vp1, off);
                }
                if (lane == 0) {
                    red_f32(&g_V[b][c0 + i], vp0);
                    red_f32(&g_V[b][c0 + i + 1], vp1);
                }
            }
        }
        if (i < rc) {        // odd tail row
            const ulonglong2* r0 = (const ulonglong2*)&buf[i * HT + half * HHALF];
            unsigned long long a00 = 0ull, a01 = 0ull;
#pragma unroll
            for (int j = 0; j < HHALF / 4; j++) {
                ulonglong2 x0 = r0[j];
                asm("fma.rn.f32x2 %0,%1,%2,%0;" : "+l"(a00) : "l"(x0.x), "l"(wk2[2*j]));
                asm("fma.rn.f32x2 %0,%1,%2,%0;" : "+l"(a01) : "l"(x0.y), "l"(wk2[2*j+1]));
            }
            float l0,h0f,l1,h1f;
            asm("mov.b64 {%0,%1},%2;" : "=f"(l0), "=f"(h0f) : "l"(a00));
            asm("mov.b64 {%0,%1},%2;" : "=f"(l1), "=f"(h1f) : "l"(a01));
            sKh[i * DD + d] = (l0 + h0f) + (l1 + h1f);
            if (tid < HT) {
                float vp0 = buf[i * HT + tid] * swr[tid];
#pragma unroll
                for (int off = 16; off; off >>= 1)
                    vp0 += __shfl_down_sync(0xffffffffu, vp0, off);
                if (lane == 0) red_f32(&g_V[b][c0 + i], vp0);
            }
        }

        // Q: if the last sentence row lives in this chunk (buf still valid)
        if (last >= c0 && last < c0 + rc) {
            const float* srow = &buf[(last - c0) * HT + half * HHALF];
            float aq0 = 0.0f, aq1 = 0.0f;
#pragma unroll
            for (int j = 0; j < HHALF; j += 2) {
                aq0 += srow[j]     * Wq[(size_t)(hb + j) * DD + d];
                aq1 += srow[j + 1] * Wq[(size_t)(hb + j + 1) * DD + d];
            }
            red_f32(&g_Q[b][d], aq0 + aq1);
        }
        __syncthreads();

        // combine halves + single v2-RED per (row,d)
        {
            const float2* p0 = (const float2*)sK0;
            const float2* p1 = (const float2*)sK1;
            int tot2 = rc * (DD / 2);
            for (int e = tid; e < tot2; e += TPB) {
                int row = e >> 6, ph = e & 63;
                float2 v0 = p0[e], v1 = p1[e];
                red_v2(&g_K[b][c0 + row][2 * ph], v0.x + v1.x, v0.y + v1.y);
            }
        }
        __syncthreads();   // sK/buf reusable next chunk
    }

    // ---- per-batch arrival: 64th block proceeds to attention ----
    __threadfence();
    __syncthreads();
    if (tid == 0) {
        int old = atomicAdd(&g_arrive[b], 1);
        s_last = (old == ARR_TARGET - 1);
        if (s_last) g_arrive[b] = 0;     // reset for next replay
    }
    __syncthreads();
    if (!s_last) return;
    __threadfence();                     // acquire: make all REDs visible

    // =================== attention tail (1 block per batch) ================
    // burst g_K[b] into pool; zero it behind the read
    {
        float4* b4 = (float4*)pool;
        float4 z = make_float4(0.f, 0.f, 0.f, 0.f);
        int tot = cnt * (DD / 4);
        for (int ii = tid; ii < tot; ii += TPB) {
            int row = ii >> 5, c4 = ii & 31;
            float4 v = *(const float4*)&g_K[b][row][c4 * 4];
            b4[ii] = v;
            *(float4*)&g_K[b][row][c4 * 4] = z;
        }
    }
    if (tid < NMAX) { sv[tid] = g_V[b][tid]; g_V[b][tid] = 0.0f; }

    const float LN_THETA = 9.210340371976184f;   // ln(10000)

    // RoPE the single q row at rank = last; zero g_Q behind the read
    if (tid < DD) {
        float freq = __expf(-LN_THETA * (float)(2 * (tid >> 1)) * (1.0f / 128.0f));
        float qv = g_Q[b][tid] + bq[tid];
        g_Q[b][tid] = 0.0f;
        float a = (float)last * freq;
        float cq = __cosf(a), sq = __sinf(a);
        float qp = __shfl_xor_sync(0xffffffffu, qv, 1);
        qs[tid] = ((tid & 1) == 0) ? (qv * cq - qp * sq) : (qp * sq + qv * cq);
    }
    __syncthreads();

    // logits from smem: warp w handles n = w, w+8, ...
    float fr[4];
#pragma unroll
    for (int s4 = 0; s4 < 4; s4++) {
        int dd = lane + s4 * 32;
        fr[s4] = __expf(-LN_THETA * (float)(2 * (dd >> 1)) * (1.0f / 128.0f));
    }
    for (int n = warp; n < cnt; n += 8) {
        float dot = 0.0f;
        float nf = (float)n;
#pragma unroll
        for (int s4 = 0; s4 < 4; s4++) {
            int dd = lane + s4 * 32;
            float kv = pool[n * DD + dd] + bk[dd];
            float a = nf * fr[s4];
            float cn = __cosf(a), sn = __sinf(a);
            float kp = __shfl_xor_sync(0xffffffffu, kv, 1);
            float kr = ((dd & 1) == 0) ? (kv * cn - kp * sn) : (kp * sn + kv * cn);
            dot += qs[dd] * kr;
        }
#pragma unroll
        for (int off = 16; off; off >>= 1)
            dot += __shfl_xor_sync(0xffffffffu, dot, off);
        if (lane == 0) lg[n] = dot * 0.08838834764831845f;  // 1/sqrt(128)
    }
    __syncthreads();

    // warp-parallel softmax + reward; then cross-batch join + loss
    if (warp == 0) {
        const float NEG = -3.0e38f;
        int n0 = lane, n1 = lane + 32;
        bool v0ok = (n0 < cnt), v1ok = (n1 < cnt);
        float l0 = v0ok ? lg[n0] : NEG;
        float l1 = v1ok ? lg[n1] : NEG;
        float mx = fmaxf(l0, l1);
#pragma unroll
        for (int off = 16; off; off >>= 1)
            mx = fmaxf(mx, __shfl_xor_sync(0xffffffffu, mx, off));

        float br0 = br[0];
        float e0 = v0ok ? __expf(l0 - mx) : 0.0f;
        float e1 = v1ok ? __expf(l1 - mx) : 0.0f;
        float vn0 = v0ok ? (sv[n0] + br0) : 0.0f;
        float vp0 = (v0ok && n0 > 0) ? (sv[n0 - 1] + br0) : 0.0f;
        float vn1 = v1ok ? (sv[n1] + br0) : 0.0f;
        float vp1 = v1ok ? (sv[n1 - 1] + br0) : 0.0f;
        float sum = e0 + e1;
        float rew = e0 * (vn0 - vp0) + e1 * (vn1 - vp1);
#pragma unroll
        for (int off = 16; off; off >>= 1) {
            sum += __shfl_xor_sync(0xffffffffu, sum, off);
            rew += __shfl_xor_sync(0xffffffffu, rew, off);
        }
        if (lane == 0) {
            g_rew[b] = rew / sum;
            __threadfence();
            int old2 = atomicAdd(&g_done, 1);
            if (old2 == BB - 1) {        // last batch: pairwise loss + output
                __threadfence();
                float r[BB];
#pragma unroll
                for (int k = 0; k < BB; k++) r[k] = g_rew[k];
                float loss = 0.0f;
#pragma unroll
                for (int k = 0; k < 4; k++) {
                    float x = r[k] - r[k + 4];
                    loss += (x >= 0.0f) ? log1pf(expf(-x))
                                        : (-x + log1pf(expf(x)));
                }
                loss *= 0.25f;
                if (out_size >= 9) {
                    out[0] = loss;
                    for (int k = 0; k < 8; k++) out[1 + k] = r[k];
                } else if (out_size == 8) {
                    for (int k = 0; k < 8; k++) out[k] = r[k];
                } else {
                    out[0] = loss;
                }
                g_done = 0;              // reset for next replay
            }
        }
    }
}

// ---------------------------------------------------------------------------
extern "C" void kernel_launch(void* const* d_in, const int* in_sizes, int n_in,
                              void* d_out, int out_size) {
    const float* hid  = (const float*)d_in[0];
    const int*   mask = (const int*)  d_in[1];
    const float* Wq   = (const float*)d_in[2];
    const float* bq   = (const float*)d_in[3];
    const float* Wk   = (const float*)d_in[4];
    const float* bk   = (const float*)d_in[5];
    const float* Wr   = (const float*)d_in[6];
    const float* br   = (const float*)d_in[7];
    float* out = (float*)d_out;

    k_fused<<<dim3(NT, BB), TPB>>>(hid, mask, Wq, bq, Wk, bk, Wr, br,
                                   out, out_size);
}

// round 14
// speedup vs baseline: 1.2708x; 1.2636x over previous
#include <cuda_runtime.h>
#include <math.h>
#include <stdint.h>

#define BB 8
#define SS 4096
#define HH 4096
#define DD 128
#define NMAX 64
#define NT 64            /* k-slices (h tiles of 64) */
#define HT 64
#define TPB 128
#define MROWS 48         /* MMA-covered rows (3 m-tiles of 16) */
#define AS 68            /* padded A row stride (floats): conflict-free frags */
#define ARR_TARGET NT

// -------- persistent scratch: zero at load; tail re-zeros each replay ------
__device__ float g_K[BB][NMAX][DD];
__device__ float g_Q[BB][DD];
__device__ float g_V[BB][NMAX];
__device__ float g_rew[BB];
__device__ int   g_arrive[BB];
__device__ int   g_done;

__device__ __forceinline__ void red_f32(float* p, float v) {
    asm volatile("red.global.add.f32 [%0], %1;" :: "l"(p), "f"(v) : "memory");
}
__device__ __forceinline__ void red_v2(float* p, float x, float y) {
    asm volatile("red.global.add.v2.f32 [%0], {%1,%2};"
                 :: "l"(p), "f"(x), "f"(y) : "memory");
}
__device__ __forceinline__ uint32_t f2tf(float f) {
    uint32_t u; asm("cvt.rna.tf32.f32 %0,%1;" : "=r"(u) : "f"(f)); return u;
}

#define MMA(c0,c1,c2,c3,a0,a1,a2,a3,b0,b1)                                 \
    asm volatile("mma.sync.aligned.m16n8k8.row.col.f32.tf32.tf32.f32 "     \
        "{%0,%1,%2,%3},{%4,%5,%6,%7},{%8,%9},{%0,%1,%2,%3};"               \
        : "+f"(c0), "+f"(c1), "+f"(c2), "+f"(c3)                           \
        : "r"(a0), "r"(a1), "r"(a2), "r"(a3), "r"(b0), "r"(b1))

// ---------------------------------------------------------------------------
// ONE fused kernel. grid=(NT, BB), 128 threads (4 warps).
// Phase 1: gather 41 sentence-row slices to smem as tf32 hi/lo split;
//          K-projection via m16n8k8 tf32 MMA (3-term split-fp32 accuracy);
//          warp w owns n-tiles [4w,4w+4), all 3 m-tiles, 8 k-steps.
//          C flushed as v2-RED burst. V/Q scalar as before.
// Phase 2 (64th block of a batch): attention + reward + re-zero.
// Phase 3 (last batch): pairwise loss + output.
// ---------------------------------------------------------------------------
__global__ void __launch_bounds__(TPB)
k_fused(const float* __restrict__ hid,
        const int*   __restrict__ mask,
        const float* __restrict__ Wq,
        const float* __restrict__ bq,
        const float* __restrict__ Wk,
        const float* __restrict__ bk,
        const float* __restrict__ Wr,
        const float* __restrict__ br,
        float* __restrict__ out, int out_size) {
    const int b    = blockIdx.y;
    const int tile = blockIdx.x;
    const int h0   = tile * HT;
    const int tid  = threadIdx.x;
    const int lane = tid & 31, warp = tid >> 5;
    const int qid  = lane >> 2, qli = lane & 3;   // quad id / quad lane

    // pool: Ahi = pool[0 : 64*AS), Alo = pool[64*AS : 2*64*AS)  (34.8 KB)
    // tail reuses pool[0 : cnt*DD) for K (max 32 KB <= 34.8 KB)
    __shared__ __align__(16) float pool[2 * NMAX * AS];
    float* Ahi = pool;
    float* Alo = pool + NMAX * AS;
    __shared__ float swr[HT];
    __shared__ float qs[DD];
    __shared__ float lg[NMAX];
    __shared__ float sv[NMAX];
    __shared__ int   s_pos[NMAX];
    __shared__ int   s_wsum[4];
    __shared__ int   s_cnt;
    __shared__ int   s_last;

    if (tid < HT) swr[tid] = Wr[h0 + tid];

    // ---- mask scan: single pass, 128 threads x 32 elements ----
    {
        const int base = tid * 32;
        const int4* m4 = (const int4*)(mask + b * SS + base);
        int v[32];
#pragma unroll
        for (int q = 0; q < 8; q++) {
            int4 t4 = m4[q];
            v[4*q] = t4.x; v[4*q+1] = t4.y; v[4*q+2] = t4.z; v[4*q+3] = t4.w;
        }
        int c = 0;
#pragma unroll
        for (int j = 0; j < 32; j++) c += (v[j] > 0);
        int x = c;
#pragma unroll
        for (int off = 1; off < 32; off <<= 1) {
            int y = __shfl_up_sync(0xffffffffu, x, off);
            if (lane >= off) x += y;
        }
        if (lane == 31) s_wsum[warp] = x;
        __syncthreads();
        int pre = 0;
#pragma unroll
        for (int w = 0; w < 4; w++) pre += (w < warp) ? s_wsum[w] : 0;
        int r = pre + x - c;
#pragma unroll
        for (int j = 0; j < 32; j++) {
            if (v[j] > 0) { if (r < NMAX) s_pos[r] = base + j; r++; }
        }
        if (tid == 0) {
            int tot = s_wsum[0] + s_wsum[1] + s_wsum[2] + s_wsum[3];
            s_cnt = (tot < NMAX) ? tot : NMAX;
        }
        __syncthreads();
    }
    const int cnt  = s_cnt;
    const int last = cnt - 1;
    const int rmax = (cnt > MROWS) ? cnt : MROWS;

    // ---- gather rows -> smem, split into tf32 hi/lo (zero-pad to MROWS) ----
    for (int i = tid; i < rmax * (HT / 4); i += TPB) {
        int row = i >> 4;            // HT/4 = 16 float4 per row
        int c4  = i & 15;
        float4 v;
        if (row < cnt)
            v = *(const float4*)(hid + ((size_t)b * SS + s_pos[row]) * HH
                                     + h0 + c4 * 4);
        else
            v = make_float4(0.f, 0.f, 0.f, 0.f);
        float f[4] = {v.x, v.y, v.z, v.w};
        int base = row * AS + c4 * 4;
#pragma unroll
        for (int e = 0; e < 4; e++) {
            uint32_t hb2 = f2tf(f[e]);
            float hf = __uint_as_float(hb2);
            uint32_t lb = f2tf(f[e] - hf);
            Ahi[base + e] = hf;
            Alo[base + e] = __uint_as_float(lb);
        }
    }
    __syncthreads();

    // ---- V: warp handles rows r = warp, warp+4, ... ----
    for (int r = warp; r < cnt; r += 4) {
        float a0 = Ahi[r * AS + lane]      + Alo[r * AS + lane];
        float a1 = Ahi[r * AS + 32 + lane] + Alo[r * AS + 32 + lane];
        float v = a0 * swr[lane] + a1 * swr[lane + 32];
#pragma unroll
        for (int off = 16; off; off >>= 1)
            v += __shfl_down_sync(0xffffffffu, v, off);
        if (lane == 0) red_f32(&g_V[b][r], v);
    }

    // ---- Q: thread d = tid, full 64-h slice of the last row ----
    {
        float aq = 0.0f;
#pragma unroll 8
        for (int h = 0; h < HT; h++) {
            float a = Ahi[last * AS + h] + Alo[last * AS + h];
            aq += a * Wq[(size_t)(h0 + h) * DD + tid];
        }
        float pq = __shfl_xor_sync(0xffffffffu, aq, 1);
        if ((tid & 1) == 0) red_v2(&g_Q[b][tid], aq, pq);
    }

    // ---- K-projection: tf32 MMA, 3-term split ----
    float C[3][4][4];
#pragma unroll
    for (int mt = 0; mt < 3; mt++)
#pragma unroll
        for (int t = 0; t < 4; t++)
#pragma unroll
            for (int e = 0; e < 4; e++) C[mt][t][e] = 0.0f;

#pragma unroll 2
    for (int kt = 0; kt < 8; kt++) {
        // B fragments: warp's 4 n-tiles, rows kt*8+qli (+4), col qid
        uint32_t bh0[4], bh1[4], bl0[4], bl1[4];
#pragma unroll
        for (int t = 0; t < 4; t++) {
            int col = (warp * 4 + t) * 8 + qid;
            size_t r0 = (size_t)(h0 + kt * 8 + qli) * DD + col;
            float bv0 = Wk[r0];
            float bv1 = Wk[r0 + 4 * DD];
            bh0[t] = f2tf(bv0);
            bl0[t] = f2tf(bv0 - __uint_as_float(bh0[t]));
            bh1[t] = f2tf(bv1);
            bl1[t] = f2tf(bv1 - __uint_as_float(bh1[t]));
        }
        // A fragments: 3 m-tiles, hi & lo
        uint32_t ah[3][4], al[3][4];
#pragma unroll
        for (int mt = 0; mt < 3; mt++) {
            int base = (mt * 16 + qid) * AS + kt * 8 + qli;
            ah[mt][0] = __float_as_uint(Ahi[base]);
            ah[mt][1] = __float_as_uint(Ahi[base + 8 * AS]);
            ah[mt][2] = __float_as_uint(Ahi[base + 4]);
            ah[mt][3] = __float_as_uint(Ahi[base + 8 * AS + 4]);
            al[mt][0] = __float_as_uint(Alo[base]);
            al[mt][1] = __float_as_uint(Alo[base + 8 * AS]);
            al[mt][2] = __float_as_uint(Alo[base + 4]);
            al[mt][3] = __float_as_uint(Alo[base + 8 * AS + 4]);
        }
#pragma unroll
        for (int mt = 0; mt < 3; mt++)
#pragma unroll
            for (int t = 0; t < 4; t++) {
                MMA(C[mt][t][0], C[mt][t][1], C[mt][t][2], C[mt][t][3],
                    ah[mt][0], ah[mt][1], ah[mt][2], ah[mt][3],
                    bh0[t], bh1[t]);
                MMA(C[mt][t][0], C[mt][t][1], C[mt][t][2], C[mt][t][3],
                    ah[mt][0], ah[mt][1], ah[mt][2], ah[mt][3],
                    bl0[t], bl1[t]);
                MMA(C[mt][t][0], C[mt][t][1], C[mt][t][2], C[mt][t][3],
                    al[mt][0], al[mt][1], al[mt][2], al[mt][3],
                    bh0[t], bh1[t]);
            }
    }

    // ---- flush C with v2-RED burst (rows < cnt only) ----
#pragma unroll
    for (int mt = 0; mt < 3; mt++) {
        int r0 = mt * 16 + qid;
#pragma unroll
        for (int t = 0; t < 4; t++) {
            int col = (warp * 4 + t) * 8 + 2 * qli;
            if (r0 < cnt)
                red_v2(&g_K[b][r0][col], C[mt][t][0], C[mt][t][1]);
            if (r0 + 8 < cnt)
                red_v2(&g_K[b][r0 + 8][col], C[mt][t][2], C[mt][t][3]);
        }
    }

    // ---- scalar fallback for rows >= MROWS (never taken when cnt<=48) ----
    for (int n = MROWS; n < cnt; n++) {
        float acc = 0.0f;
        for (int h = 0; h < HT; h++) {
            float a = Ahi[n * AS + h] + Alo[n * AS + h];
            acc += a * Wk[(size_t)(h0 + h) * DD + tid];
        }
        red_f32(&g_K[b][n][tid], acc);
    }

    // ---- per-batch arrival: 64th block proceeds to attention ----
    __threadfence();
    __syncthreads();
    if (tid == 0) {
        int old = atomicAdd(&g_arrive[b], 1);
        s_last = (old == ARR_TARGET - 1);
        if (s_last) g_arrive[b] = 0;
    }
    __syncthreads();
    if (!s_last) return;
    __threadfence();                     // acquire: make all REDs visible

    // =================== attention tail (1 block per batch) ================
    {
        float4* b4 = (float4*)pool;
        float4 z = make_float4(0.f, 0.f, 0.f, 0.f);
        int tot = cnt * (DD / 4);
        for (int ii = tid; ii < tot; ii += TPB) {
            int row = ii >> 5, c4 = ii & 31;
            float4 v = *(const float4*)&g_K[b][row][c4 * 4];
            b4[ii] = v;
            *(float4*)&g_K[b][row][c4 * 4] = z;
        }
    }
    if (tid < NMAX) { sv[tid] = g_V[b][tid]; g_V[b][tid] = 0.0f; }

    const float LN_THETA = 9.210340371976184f;   // ln(10000)

    {
        float freq = __expf(-LN_THETA * (float)(2 * (tid >> 1)) * (1.0f / 128.0f));
        float qv = g_Q[b][tid] + bq[tid];
        g_Q[b][tid] = 0.0f;
        float a = (float)last * freq;
        float cq = __cosf(a), sq = __sinf(a);
        float qp = __shfl_xor_sync(0xffffffffu, qv, 1);
        qs[tid] = ((tid & 1) == 0) ? (qv * cq - qp * sq) : (qp * sq + qv * cq);
    }
    __syncthreads();

    float fr[4];
#pragma unroll
    for (int s4 = 0; s4 < 4; s4++) {
        int dd = lane + s4 * 32;
        fr[s4] = __expf(-LN_THETA * (float)(2 * (dd >> 1)) * (1.0f / 128.0f));
    }
    for (int n = warp; n < cnt; n += 4) {
        float dot = 0.0f;
        float nf = (float)n;
#pragma unroll
        for (int s4 = 0; s4 < 4; s4++) {
            int dd = lane + s4 * 32;
            float kv = pool[n * DD + dd] + bk[dd];
            float a = nf * fr[s4];
            float cn = __cosf(a), sn = __sinf(a);
            float kp = __shfl_xor_sync(0xffffffffu, kv, 1);
            float kr = ((dd & 1) == 0) ? (kv * cn - kp * sn) : (kp * sn + kv * cn);
            dot += qs[dd] * kr;
        }
#pragma unroll
        for (int off = 16; off; off >>= 1)
            dot += __shfl_xor_sync(0xffffffffu, dot, off);
        if (lane == 0) lg[n] = dot * 0.08838834764831845f;  // 1/sqrt(128)
    }
    __syncthreads();

    if (warp == 0) {
        const float NEG = -3.0e38f;
        int n0 = lane, n1 = lane + 32;
        bool v0ok = (n0 < cnt), v1ok = (n1 < cnt);
        float l0 = v0ok ? lg[n0] : NEG;
        float l1 = v1ok ? lg[n1] : NEG;
        float mx = fmaxf(l0, l1);
#pragma unroll
        for (int off = 16; off; off >>= 1)
            mx = fmaxf(mx, __shfl_xor_sync(0xffffffffu, mx, off));

        float br0 = br[0];
        float e0 = v0ok ? __expf(l0 - mx) : 0.0f;
        float e1 = v1ok ? __expf(l1 - mx) : 0.0f;
        float vn0 = v0ok ? (sv[n0] + br0) : 0.0f;
        float vp0 = (v0ok && n0 > 0) ? (sv[n0 - 1] + br0) : 0.0f;
        float vn1 = v1ok ? (sv[n1] + br0) : 0.0f;
        float vp1 = v1ok ? (sv[n1 - 1] + br0) : 0.0f;
        float sum = e0 + e1;
        float rew = e0 * (vn0 - vp0) + e1 * (vn1 - vp1);
#pragma unroll
        for (int off = 16; off; off >>= 1) {
            sum += __shfl_xor_sync(0xffffffffu, sum, off);
            rew += __shfl_xor_sync(0xffffffffu, rew, off);
        }
        if (lane == 0) {
            g_rew[b] = rew / sum;
            __threadfence();
            int old2 = atomicAdd(&g_done, 1);
            if (old2 == BB - 1) {
                __threadfence();
                float r[BB];
#pragma unroll
                for (int k = 0; k < BB; k++) r[k] = g_rew[k];
                float loss = 0.0f;
#pragma unroll
                for (int k = 0; k < 4; k++) {
                    float x = r[k] - r[k + 4];
                    loss += (x >= 0.0f) ? log1pf(expf(-x))
                                        : (-x + log1pf(expf(x)));
                }
                loss *= 0.25f;
                if (out_size >= 9) {
                    out[0] = loss;
                    for (int k = 0; k < 8; k++) out[1 + k] = r[k];
                } else if (out_size == 8) {
                    for (int k = 0; k < 8; k++) out[k] = r[k];
                } else {
                    out[0] = loss;
                }
                g_done = 0;
            }
        }
    }
}

// ---------------------------------------------------------------------------
extern "C" void kernel_launch(void* const* d_in, const int* in_sizes, int n_in,
                              void* d_out, int out_size) {
    const float* hid  = (const float*)d_in[0];
    const int*   mask = (const int*)  d_in[1];
    const float* Wq   = (const float*)d_in[2];
    const float* bq   = (const float*)d_in[3];
    const float* Wk   = (const float*)d_in[4];
    const float* bk   = (const float*)d_in[5];
    const float* Wr   = (const float*)d_in[6];
    const float* br   = (const float*)d_in[7];
    float* out = (float*)d_out;

    k_fused<<<dim3(NT, BB), TPB>>>(hid, mask, Wq, bq, Wk, bk, Wr, br,
                                   out, out_size);
}